// round 7
// baseline (speedup 1.0000x reference)
#include <cuda_runtime.h>
#include <math.h>

#define EPSF 1.1920929e-07f
typedef unsigned long long ull;

// ---------------- f32x2 packed-FMA helpers (sm_103a) ----------------
__device__ __forceinline__ ull f2pk(float a, float b) {
    ull r; asm("mov.b64 %0, {%1,%2};" : "=l"(r) : "f"(a), "f"(b)); return r;
}
__device__ __forceinline__ ull ffma2(ull a, ull b, ull c) {
    ull d; asm("fma.rn.f32x2 %0, %1, %2, %3;" : "=l"(d) : "l"(a), "l"(b), "l"(c)); return d;
}
__device__ __forceinline__ float2 f2up(ull v) {
    float2 f; asm("mov.b64 {%0,%1}, %2;" : "=f"(f.x), "=f"(f.y) : "l"(v)); return f;
}

// ---------------- scratch (__device__ globals; no allocations) ----------------
__device__ float d_logits[4096];                 // (8,512)
__device__ int   d_topk[32];                     // (8,4) sorted ascending
__device__ float d_Qb[8 * 8 * 65 * 128];         // (bh, s, c) rope+rms+tao q
__device__ float d_KbT[64 * 128 * 65];           // (bh, c, s) TRANSPOSED k
__device__ float d_Vb[8 * 8 * 65 * 128];         // (bh, s, c)
__device__ float d_g[8 * 64 * 1024];             // gate logits (b, r, h, c)
__device__ float d_yg[8 * 64 * 1024];            // gated attention output

// ---------------- K1: per-patch score logit; one warp per patch ----------------
__global__ __launch_bounds__(256) void k_score(const float* __restrict__ x,
                                               const float* __restrict__ pw) {
    int wid = threadIdx.x >> 5, lane = threadIdx.x & 31;
    int pid = blockIdx.x * 8 + wid;              // 512 blocks * 8 warps = 4096 patches
    const float4* xv = (const float4*)(x + (size_t)pid * 2048);
    const float4* pv = (const float4*)pw;
    float ss = 0.f, dp = 0.f;
#pragma unroll
    for (int i = 0; i < 16; i++) {
        float4 v = xv[i * 32 + lane];
        float4 w = pv[i * 32 + lane];
        ss += v.x * v.x + v.y * v.y + v.z * v.z + v.w * v.w;
        dp += v.x * w.x + v.y * w.y + v.z * w.z + v.w * w.w;
    }
#pragma unroll
    for (int o = 16; o; o >>= 1) {
        ss += __shfl_xor_sync(0xffffffffu, ss, o);
        dp += __shfl_xor_sync(0xffffffffu, dp, o);
    }
    if (lane == 0) d_logits[pid] = dp * rsqrtf(ss * (1.0f / 2048.0f) + EPSF);
}

// ---------------- K2: block0 = top-4 per batch; block1 = sink rows ----------------
__global__ __launch_bounds__(256) void k_topk_sink(const float* __restrict__ sink,
                                                   const float* __restrict__ tao) {
    int wid = threadIdx.x >> 5, lane = threadIdx.x & 31;
    if (blockIdx.x == 0) {
        int b = wid;
        float v[16];
#pragma unroll
        for (int i = 0; i < 16; i++) v[i] = d_logits[b * 512 + i * 32 + lane];
        int got[4];
#pragma unroll
        for (int r = 0; r < 4; r++) {
            float bv = -1e30f; int bi = 1 << 30;
#pragma unroll
            for (int i = 0; i < 16; i++) {
                int idx = i * 32 + lane;
                if (v[i] > bv || (v[i] == bv && idx < bi)) { bv = v[i]; bi = idx; }
            }
#pragma unroll
            for (int o = 16; o; o >>= 1) {
                float ov = __shfl_xor_sync(0xffffffffu, bv, o);
                int   oi = __shfl_xor_sync(0xffffffffu, bi, o);
                if (ov > bv || (ov == bv && oi < bi)) { bv = ov; bi = oi; }
            }
            got[r] = bi;
            if ((bi & 31) == lane) v[bi >> 5] = -1e30f;
        }
        if (lane == 0) {
#pragma unroll
            for (int i = 0; i < 4; i++)
#pragma unroll
                for (int j = 0; j < 3; j++)
                    if (got[j + 1] < got[j]) { int t = got[j]; got[j] = got[j + 1]; got[j + 1] = t; }
#pragma unroll
            for (int i = 0; i < 4; i++) d_topk[b * 4 + i] = got[i];
        }
    } else {
        // sink row s=0 per head (rope at s=0 is identity): Q/K = rmsnorm(sink)*tao, V = sink
        int h = wid;
        int c0 = lane * 4;
        float4 v = *(const float4*)(sink + h * 128 + c0);
        float ss = v.x * v.x + v.y * v.y + v.z * v.z + v.w * v.w;
#pragma unroll
        for (int o = 16; o; o >>= 1) ss += __shfl_xor_sync(0xffffffffu, ss, o);
        float n = rsqrtf(ss * (1.f / 128.f) + EPSF);
        float nq = n * tao[0], nk = n * tao[1];
        float4 q = make_float4(v.x * nq, v.y * nq, v.z * nq, v.w * nq);
#pragma unroll
        for (int b = 0; b < 8; b++) {
            int bh = b * 8 + h;
            size_t off = ((size_t)(bh * 65)) * 128 + c0;
            *(float4*)(d_Qb + off) = q;
            *(float4*)(d_Vb + off) = v;
            size_t tb = ((size_t)bh * 128 + c0) * 65;      // s = 0
            d_KbT[tb]            = v.x * nk;
            d_KbT[tb + 65]       = v.y * nk;
            d_KbT[tb + 130]      = v.z * nk;
            d_KbT[tb + 195]      = v.w * nk;
        }
    }
}

// ---------------- K3: qkvg GEMM fused with rope+rmsnorm+tao epilogue ----------------
// grid (32 n-tiles, 8 batches), 256 threads; tile M=64 x N=128, K chunks of 32.
__global__ __launch_bounds__(256) void k_qkvg(const float* __restrict__ x,
                                              const float* __restrict__ W,
                                              const float* __restrict__ cosb,
                                              const float* __restrict__ sinb,
                                              const float* __restrict__ tao) {
    int nt = blockIdx.x, b = blockIdx.y;
    int tid = threadIdx.x;
    __shared__ __align__(16) float Xs[32][68];    // [k][m]
    __shared__ __align__(16) float Ws[32][132];   // [k][n]
    __shared__ int toks[64];
    if (tid < 64) toks[tid] = d_topk[b * 4 + (tid >> 4)] * 16 + (tid & 15);
    __syncthreads();
    int tx = tid & 15, ty = tid >> 4;
    int m0 = ty * 4, n0 = tx * 8;
    ull acc[4][4];
#pragma unroll
    for (int i = 0; i < 4; i++)
#pragma unroll
        for (int j = 0; j < 4; j++) acc[i][j] = 0ull;

#pragma unroll 1
    for (int kc = 0; kc < 4; kc++) {
#pragma unroll
        for (int jj = 0; jj < 2; jj++) {
            int idx = tid + jj * 256;
            int m = idx >> 3, kq = idx & 7;
            float4 v = *(const float4*)(x + ((size_t)(b * 8192 + toks[m])) * 128 + kc * 32 + kq * 4);
            Xs[kq * 4 + 0][m] = v.x; Xs[kq * 4 + 1][m] = v.y;
            Xs[kq * 4 + 2][m] = v.z; Xs[kq * 4 + 3][m] = v.w;
        }
#pragma unroll
        for (int jj = 0; jj < 4; jj++) {
            int idx = tid + jj * 256;
            int c = idx >> 3, kq = idx & 7;
            float4 v = *(const float4*)(W + ((size_t)(nt * 128 + c)) * 128 + kc * 32 + kq * 4);
            Ws[kq * 4 + 0][c] = v.x; Ws[kq * 4 + 1][c] = v.y;
            Ws[kq * 4 + 2][c] = v.z; Ws[kq * 4 + 3][c] = v.w;
        }
        __syncthreads();
#pragma unroll
        for (int k = 0; k < 32; k++) {
            float4 xv = *(const float4*)&Xs[k][m0];
            ull xb0 = f2pk(xv.x, xv.x), xb1 = f2pk(xv.y, xv.y);
            ull xb2 = f2pk(xv.z, xv.z), xb3 = f2pk(xv.w, xv.w);
            const ull* wp = (const ull*)&Ws[k][n0];
            ull w0 = wp[0], w1 = wp[1], w2 = wp[2], w3 = wp[3];
            acc[0][0] = ffma2(xb0, w0, acc[0][0]); acc[0][1] = ffma2(xb0, w1, acc[0][1]);
            acc[0][2] = ffma2(xb0, w2, acc[0][2]); acc[0][3] = ffma2(xb0, w3, acc[0][3]);
            acc[1][0] = ffma2(xb1, w0, acc[1][0]); acc[1][1] = ffma2(xb1, w1, acc[1][1]);
            acc[1][2] = ffma2(xb1, w2, acc[1][2]); acc[1][3] = ffma2(xb1, w3, acc[1][3]);
            acc[2][0] = ffma2(xb2, w0, acc[2][0]); acc[2][1] = ffma2(xb2, w1, acc[2][1]);
            acc[2][2] = ffma2(xb2, w2, acc[2][2]); acc[2][3] = ffma2(xb2, w3, acc[2][3]);
            acc[3][0] = ffma2(xb3, w0, acc[3][0]); acc[3][1] = ffma2(xb3, w1, acc[3][1]);
            acc[3][2] = ffma2(xb3, w2, acc[3][2]); acc[3][3] = ffma2(xb3, w3, acc[3][3]);
        }
        __syncthreads();
    }

    // ---- fused epilogue ----
    int cb = nt >> 3, h = nt & 7;
    int cat = ty & 3;                             // 0=q 1=k 2=v 3=g (half-warp-uniform)
    int p = ty >> 2;
    int bh = b * 8 + h;
#pragma unroll
    for (int i = 0; i < 4; i++) {
        float r[8];
#pragma unroll
        for (int j = 0; j < 4; j++) {
            float2 f = f2up(acc[i][j]);
            r[2 * j] = f.x; r[2 * j + 1] = f.y;
        }
        int s0 = p * 16 + i * 4 + cb;             // row index within (b,h), 0..63
        int s = s0 + 1;
        if (cat < 2) {                            // q or k: rope + rmsnorm + tao
            float other[8];
#pragma unroll
            for (int c = 0; c < 8; c++) other[c] = __shfl_xor_sync(0xffffffffu, r[c], 8);
            int d0 = n0 & 63;
            float4 ca = *(const float4*)(cosb + s * 64 + d0);
            float4 cbv = *(const float4*)(cosb + s * 64 + d0 + 4);
            float4 sa = *(const float4*)(sinb + s * 64 + d0);
            float4 sb = *(const float4*)(sinb + s * 64 + d0 + 4);
            float cs[8] = {ca.x, ca.y, ca.z, ca.w, cbv.x, cbv.y, cbv.z, cbv.w};
            float sn[8] = {sa.x, sa.y, sa.z, sa.w, sb.x, sb.y, sb.z, sb.w};
            float sgn = (tx < 8) ? 1.f : -1.f;
            float rv[8], ssq = 0.f;
#pragma unroll
            for (int c = 0; c < 8; c++) {
                rv[c] = fmaf(r[c], cs[c], sgn * other[c] * sn[c]);
                ssq += rv[c] * rv[c];
            }
#pragma unroll
            for (int o = 8; o; o >>= 1) ssq += __shfl_xor_sync(0xffffffffu, ssq, o);
            float nrm = rsqrtf(ssq * (1.f / 128.f) + EPSF) * tao[cat];
            if (cat == 0) {
                float* dst = d_Qb + ((size_t)bh * 65 + s) * 128 + n0;
                *(float4*)dst = make_float4(rv[0] * nrm, rv[1] * nrm, rv[2] * nrm, rv[3] * nrm);
                *(float4*)(dst + 4) = make_float4(rv[4] * nrm, rv[5] * nrm, rv[6] * nrm, rv[7] * nrm);
            } else {                               // k: write TRANSPOSED (bh, c, s)
                float* dstT = d_KbT + ((size_t)bh * 128 + n0) * 65 + s;
#pragma unroll
                for (int j = 0; j < 8; j++) dstT[j * 65] = rv[j] * nrm;
            }
        } else if (cat == 2) {                    // v: raw
            float* dst = d_Vb + ((size_t)bh * 65 + s) * 128 + n0;
            *(float4*)dst = make_float4(r[0], r[1], r[2], r[3]);
            *(float4*)(dst + 4) = make_float4(r[4], r[5], r[6], r[7]);
        } else {                                  // g: raw gate logits
            float* dst = d_g + ((size_t)(b * 64 + s0)) * 1024 + h * 128 + n0;
            *(float4*)dst = make_float4(r[0], r[1], r[2], r[3]);
            *(float4*)(dst + 4) = make_float4(r[4], r[5], r[6], r[7]);
        }
    }
}

// ---------------- K5: warp-synchronous causal attention ----------------
// grid (4 rowblocks, 64 bh), 128 threads; each warp owns 4 query rows.
// Lane = key index t (t=lane, t=lane+32 for hi blocks, plus uniform extra t=te).
// No smem, no __syncthreads.
__global__ __launch_bounds__(128) void k_attn() {
    int wid = threadIdx.x >> 5, lane = threadIdx.x & 31;
    int rb = blockIdx.x, bh = blockIdx.y;
    int b = bh >> 3, h = bh & 7;
    int r0 = rb * 16 + wid * 4;                  // rows r0..r0+3 (s = r+1)
    bool hi = (rb >= 2);
    int te = hi ? 64 : 32;
    const float* Qg = d_Qb + (size_t)bh * 65 * 128;
    const float* KT = d_KbT + (size_t)bh * 128 * 65;
    const float* Vg = d_Vb + (size_t)bh * 65 * 128;

    float4 q[4];
#pragma unroll
    for (int i = 0; i < 4; i++)
        q[i] = *(const float4*)(Qg + (size_t)(r0 + i + 1) * 128 + lane * 4);

    ull a0_01 = 0, a0_23 = 0, a1_01 = 0, a1_23 = 0, ae_01 = 0, ae_23 = 0;
#pragma unroll 4
    for (int sl = 0; sl < 32; sl++) {
        float qs[4][4];
#pragma unroll
        for (int i = 0; i < 4; i++) {
            qs[i][0] = __shfl_sync(0xffffffffu, q[i].x, sl);
            qs[i][1] = __shfl_sync(0xffffffffu, q[i].y, sl);
            qs[i][2] = __shfl_sync(0xffffffffu, q[i].z, sl);
            qs[i][3] = __shfl_sync(0xffffffffu, q[i].w, sl);
        }
#pragma unroll
        for (int cc = 0; cc < 4; cc++) {
            const float* kc = KT + (size_t)(sl * 4 + cc) * 65;
            float k0 = kc[lane];
            float ke = kc[te];
            ull qa = f2pk(qs[0][cc], qs[1][cc]);
            ull qb = f2pk(qs[2][cc], qs[3][cc]);
            ull kb0 = f2pk(k0, k0), kbe = f2pk(ke, ke);
            a0_01 = ffma2(qa, kb0, a0_01); a0_23 = ffma2(qb, kb0, a0_23);
            ae_01 = ffma2(qa, kbe, ae_01); ae_23 = ffma2(qb, kbe, ae_23);
            if (hi) {
                float k1 = kc[lane + 32];
                ull kb1 = f2pk(k1, k1);
                a1_01 = ffma2(qa, kb1, a1_01); a1_23 = ffma2(qb, kb1, a1_23);
            }
        }
    }

    const float scl = 0.08838834764831845f;      // 1/sqrt(128)
    float s0v[4], s1v[4], sev[4];
    { float2 f;
      f = f2up(a0_01); s0v[0] = f.x; s0v[1] = f.y;
      f = f2up(a0_23); s0v[2] = f.x; s0v[3] = f.y;
      f = f2up(a1_01); s1v[0] = f.x; s1v[1] = f.y;
      f = f2up(a1_23); s1v[2] = f.x; s1v[3] = f.y;
      f = f2up(ae_01); sev[0] = f.x; sev[1] = f.y;
      f = f2up(ae_23); sev[2] = f.x; sev[3] = f.y; }

    float p0[4], p1[4], pe[4];
#pragma unroll
    for (int i = 0; i < 4; i++) {
        int s = r0 + i + 1;
        bool v0ok = (lane <= s);
        bool v1ok = hi && (lane + 32 <= s);
        bool evok = (te <= s);
        float v0 = v0ok ? s0v[i] * scl : -1e30f;
        float v1 = v1ok ? s1v[i] * scl : -1e30f;
        float ve = evok ? sev[i] * scl : -1e30f;  // warp-uniform
        float m = fmaxf(v0, v1);
#pragma unroll
        for (int o = 16; o; o >>= 1) m = fmaxf(m, __shfl_xor_sync(0xffffffffu, m, o));
        m = fmaxf(m, ve);
        float e0 = v0ok ? __expf(v0 - m) : 0.f;
        float e1 = v1ok ? __expf(v1 - m) : 0.f;
        float ee = evok ? __expf(ve - m) : 0.f;
        float sum = e0 + e1;
#pragma unroll
        for (int o = 16; o; o >>= 1) sum += __shfl_xor_sync(0xffffffffu, sum, o);
        sum += ee;
        float inv = 1.f / sum;
        p0[i] = e0 * inv; p1[i] = e1 * inv; pe[i] = ee * inv;
    }

    // PV: lane owns channels c0..c0+3
    int c0 = lane * 4;
    ull y0[4], y1[4];
#pragma unroll
    for (int i = 0; i < 4; i++) { y0[i] = 0ull; y1[i] = 0ull; }
#pragma unroll 4
    for (int tl = 0; tl < 32; tl++) {
        const ull* vp0 = (const ull*)(Vg + (size_t)tl * 128 + c0);
        ull v00 = vp0[0], v01 = vp0[1];
#pragma unroll
        for (int i = 0; i < 4; i++) {
            float p = __shfl_sync(0xffffffffu, p0[i], tl);
            ull pb = f2pk(p, p);
            y0[i] = ffma2(pb, v00, y0[i]);
            y1[i] = ffma2(pb, v01, y1[i]);
        }
        if (hi) {
            const ull* vp1 = (const ull*)(Vg + (size_t)(tl + 32) * 128 + c0);
            ull v10 = vp1[0], v11 = vp1[1];
#pragma unroll
            for (int i = 0; i < 4; i++) {
                float p = __shfl_sync(0xffffffffu, p1[i], tl);
                ull pb = f2pk(p, p);
                y0[i] = ffma2(pb, v10, y0[i]);
                y1[i] = ffma2(pb, v11, y1[i]);
            }
        }
    }
    {   // extra slot t = te (pe is warp-uniform; 0 for rows that don't reach it)
        const ull* vpe = (const ull*)(Vg + (size_t)te * 128 + c0);
        ull ve0 = vpe[0], ve1 = vpe[1];
#pragma unroll
        for (int i = 0; i < 4; i++) {
            ull pb = f2pk(pe[i], pe[i]);
            y0[i] = ffma2(pb, ve0, y0[i]);
            y1[i] = ffma2(pb, ve1, y1[i]);
        }
    }

    // gate with sigmoid(g) and store
#pragma unroll
    for (int i = 0; i < 4; i++) {
        int r = r0 + i;
        float4 g4 = *(const float4*)(d_g + ((size_t)(b * 64 + r)) * 1024 + h * 128 + c0);
        float2 ya = f2up(y0[i]), yb = f2up(y1[i]);
        float4 o;
        o.x = ya.x / (1.f + __expf(-g4.x));
        o.y = ya.y / (1.f + __expf(-g4.y));
        o.z = yb.x / (1.f + __expf(-g4.z));
        o.w = yb.y / (1.f + __expf(-g4.w));
        *(float4*)(d_yg + ((size_t)(b * 64 + r)) * 1024 + h * 128 + c0) = o;
    }
}

// ---------------- K6: output GEMM, split-K=8, atomicAdd into out (f32x2) ----------------
__global__ __launch_bounds__(128) void k_out(const float* __restrict__ Wout,
                                             float* __restrict__ out) {
    int mt = blockIdx.x, nt = blockIdx.y, kc = blockIdx.z;
    __shared__ __align__(16) float Ys[32][68];
    __shared__ __align__(16) float Ws[32][68];
    int tid = threadIdx.x;
    int tx = tid & 7, ty = tid >> 3;
    int m0 = ty * 4, n0 = tx * 8;
    ull acc[4][4];
#pragma unroll
    for (int i = 0; i < 4; i++)
#pragma unroll
        for (int j = 0; j < 4; j++) acc[i][j] = 0ull;

#pragma unroll 1
    for (int ck = 0; ck < 4; ck++) {
        int kbase = kc * 128 + ck * 32;
#pragma unroll
        for (int jj = 0; jj < 4; jj++) {
            int idx = tid + jj * 128;
            int m = idx >> 3, kq = idx & 7;
            float4 v = *(const float4*)(d_yg + (size_t)(mt * 64 + m) * 1024 + kbase + kq * 4);
            Ys[kq * 4 + 0][m] = v.x; Ys[kq * 4 + 1][m] = v.y;
            Ys[kq * 4 + 2][m] = v.z; Ys[kq * 4 + 3][m] = v.w;
            float4 w = *(const float4*)(Wout + (size_t)(nt * 64 + m) * 1024 + kbase + kq * 4);
            Ws[kq * 4 + 0][m] = w.x; Ws[kq * 4 + 1][m] = w.y;
            Ws[kq * 4 + 2][m] = w.z; Ws[kq * 4 + 3][m] = w.w;
        }
        __syncthreads();
#pragma unroll
        for (int k = 0; k < 32; k++) {
            float4 yv = *(const float4*)&Ys[k][m0];
            ull yb0 = f2pk(yv.x, yv.x), yb1 = f2pk(yv.y, yv.y);
            ull yb2 = f2pk(yv.z, yv.z), yb3 = f2pk(yv.w, yv.w);
            const ull* wp = (const ull*)&Ws[k][n0];
            ull w0 = wp[0], w1 = wp[1], w2 = wp[2], w3 = wp[3];
            acc[0][0] = ffma2(yb0, w0, acc[0][0]); acc[0][1] = ffma2(yb0, w1, acc[0][1]);
            acc[0][2] = ffma2(yb0, w2, acc[0][2]); acc[0][3] = ffma2(yb0, w3, acc[0][3]);
            acc[1][0] = ffma2(yb1, w0, acc[1][0]); acc[1][1] = ffma2(yb1, w1, acc[1][1]);
            acc[1][2] = ffma2(yb1, w2, acc[1][2]); acc[1][3] = ffma2(yb1, w3, acc[1][3]);
            acc[2][0] = ffma2(yb2, w0, acc[2][0]); acc[2][1] = ffma2(yb2, w1, acc[2][1]);
            acc[2][2] = ffma2(yb2, w2, acc[2][2]); acc[2][3] = ffma2(yb2, w3, acc[2][3]);
            acc[3][0] = ffma2(yb3, w0, acc[3][0]); acc[3][1] = ffma2(yb3, w1, acc[3][1]);
            acc[3][2] = ffma2(yb3, w2, acc[3][2]); acc[3][3] = ffma2(yb3, w3, acc[3][3]);
        }
        __syncthreads();
    }
#pragma unroll
    for (int i = 0; i < 4; i++) {
        float* dst = out + (size_t)(mt * 64 + m0 + i) * 128 + nt * 64 + n0;
#pragma unroll
        for (int j = 0; j < 4; j++) {
            float2 f = f2up(acc[i][j]);
            atomicAdd(dst + 2 * j,     f.x);
            atomicAdd(dst + 2 * j + 1, f.y);
        }
    }
}

// ---------------- launch ----------------
extern "C" void kernel_launch(void* const* d_in, const int* in_sizes, int n_in,
                              void* d_out, int out_size) {
    const float* x     = (const float*)d_in[0];
    const float* cosb  = (const float*)d_in[1];
    const float* sinb  = (const float*)d_in[2];
    const float* sink  = (const float*)d_in[3];
    const float* Wqkvg = (const float*)d_in[4];
    const float* pw    = (const float*)d_in[5];
    const float* Wout  = (const float*)d_in[6];
    const float* tao   = (const float*)d_in[7];
    float* out = (float*)d_out;

    cudaMemsetAsync(out, 0, (size_t)out_size * sizeof(float));
    k_score<<<512, 256>>>(x, pw);
    k_topk_sink<<<2, 256>>>(sink, tao);
    k_qkvg<<<dim3(32, 8), 256>>>(x, Wqkvg, cosb, sinb, tao);
    k_attn<<<dim3(4, 64), 128>>>();
    k_out<<<dim3(8, 2, 8), 128>>>(Wout, out);
}

// round 9
// speedup vs baseline: 1.2746x; 1.2746x over previous
#include <cuda_runtime.h>
#include <math.h>

#define EPSF 1.1920929e-07f
typedef unsigned long long ull;

// ---------------- f32x2 packed-FMA helpers (sm_103a) ----------------
__device__ __forceinline__ ull f2pk(float a, float b) {
    ull r; asm("mov.b64 %0, {%1,%2};" : "=l"(r) : "f"(a), "f"(b)); return r;
}
__device__ __forceinline__ ull ffma2(ull a, ull b, ull c) {
    ull d; asm("fma.rn.f32x2 %0, %1, %2, %3;" : "=l"(d) : "l"(a), "l"(b), "l"(c)); return d;
}
__device__ __forceinline__ float2 f2up(ull v) {
    float2 f; asm("mov.b64 {%0,%1}, %2;" : "=f"(f.x), "=f"(f.y) : "l"(v)); return f;
}

// ---------------- scratch (__device__ globals; no allocations) ----------------
__device__ float d_logits[4096];                 // (8,512)
__device__ int   d_topk[32];                     // (8,4) sorted ascending
__device__ float d_Qb[8 * 8 * 65 * 128];         // (bh, s, c) rope+rms+tao q
__device__ float d_Kb[8 * 8 * 65 * 128];         // (bh, s, c)
__device__ float d_Vb[8 * 8 * 65 * 128];         // (bh, s, c)
__device__ float d_g[8 * 64 * 1024];             // gate logits (b, r, h, c)
__device__ float d_yg[8 * 64 * 1024];            // gated attention output

// ---------------- K1: per-patch score logit; one warp per patch ----------------
__global__ __launch_bounds__(256) void k_score(const float* __restrict__ x,
                                               const float* __restrict__ pw) {
    int wid = threadIdx.x >> 5, lane = threadIdx.x & 31;
    int pid = blockIdx.x * 8 + wid;              // 512 blocks * 8 warps = 4096 patches
    const float4* xv = (const float4*)(x + (size_t)pid * 2048);
    const float4* pv = (const float4*)pw;
    float ss = 0.f, dp = 0.f;
#pragma unroll
    for (int i = 0; i < 16; i++) {
        float4 v = xv[i * 32 + lane];
        float4 w = pv[i * 32 + lane];
        ss += v.x * v.x + v.y * v.y + v.z * v.z + v.w * v.w;
        dp += v.x * w.x + v.y * w.y + v.z * w.z + v.w * w.w;
    }
#pragma unroll
    for (int o = 16; o; o >>= 1) {
        ss += __shfl_xor_sync(0xffffffffu, ss, o);
        dp += __shfl_xor_sync(0xffffffffu, dp, o);
    }
    if (lane == 0) d_logits[pid] = dp * rsqrtf(ss * (1.0f / 2048.0f) + EPSF);
}

// ---------------- K2: block0 = top-4 per batch; block1 = sink rows ----------------
__global__ __launch_bounds__(256) void k_topk_sink(const float* __restrict__ sink,
                                                   const float* __restrict__ tao) {
    int wid = threadIdx.x >> 5, lane = threadIdx.x & 31;
    if (blockIdx.x == 0) {
        int b = wid;
        float v[16];
#pragma unroll
        for (int i = 0; i < 16; i++) v[i] = d_logits[b * 512 + i * 32 + lane];
        int got[4];
#pragma unroll
        for (int r = 0; r < 4; r++) {
            float bv = -1e30f; int bi = 1 << 30;
#pragma unroll
            for (int i = 0; i < 16; i++) {
                int idx = i * 32 + lane;
                if (v[i] > bv || (v[i] == bv && idx < bi)) { bv = v[i]; bi = idx; }
            }
#pragma unroll
            for (int o = 16; o; o >>= 1) {
                float ov = __shfl_xor_sync(0xffffffffu, bv, o);
                int   oi = __shfl_xor_sync(0xffffffffu, bi, o);
                if (ov > bv || (ov == bv && oi < bi)) { bv = ov; bi = oi; }
            }
            got[r] = bi;
            if ((bi & 31) == lane) v[bi >> 5] = -1e30f;
        }
        if (lane == 0) {
#pragma unroll
            for (int i = 0; i < 4; i++)
#pragma unroll
                for (int j = 0; j < 3; j++)
                    if (got[j + 1] < got[j]) { int t = got[j]; got[j] = got[j + 1]; got[j + 1] = t; }
#pragma unroll
            for (int i = 0; i < 4; i++) d_topk[b * 4 + i] = got[i];
        }
    } else {
        // sink row s=0 per head (rope at s=0 is identity): Q/K = rmsnorm(sink)*tao, V = sink
        int h = wid;
        int c0 = lane * 4;
        float4 v = *(const float4*)(sink + h * 128 + c0);
        float ss = v.x * v.x + v.y * v.y + v.z * v.z + v.w * v.w;
#pragma unroll
        for (int o = 16; o; o >>= 1) ss += __shfl_xor_sync(0xffffffffu, ss, o);
        float n = rsqrtf(ss * (1.f / 128.f) + EPSF);
        float nq = n * tao[0], nk = n * tao[1];
        float4 q = make_float4(v.x * nq, v.y * nq, v.z * nq, v.w * nq);
        float4 k = make_float4(v.x * nk, v.y * nk, v.z * nk, v.w * nk);
#pragma unroll
        for (int b = 0; b < 8; b++) {
            size_t off = ((size_t)((b * 8 + h) * 65)) * 128 + c0;
            *(float4*)(d_Qb + off) = q;
            *(float4*)(d_Kb + off) = k;
            *(float4*)(d_Vb + off) = v;
        }
    }
}

// ---------------- K3: qkvg GEMM fused with rope+rmsnorm+tao epilogue ----------------
// grid (32 n-tiles, 8 batches), 256 threads; tile M=64 x N=128, K chunks of 32.
__global__ __launch_bounds__(256) void k_qkvg(const float* __restrict__ x,
                                              const float* __restrict__ W,
                                              const float* __restrict__ cosb,
                                              const float* __restrict__ sinb,
                                              const float* __restrict__ tao) {
    int nt = blockIdx.x, b = blockIdx.y;
    int tid = threadIdx.x;
    __shared__ __align__(16) float Xs[32][68];    // [k][m]
    __shared__ __align__(16) float Ws[32][132];   // [k][n]
    __shared__ int toks[64];
    if (tid < 64) toks[tid] = d_topk[b * 4 + (tid >> 4)] * 16 + (tid & 15);
    __syncthreads();
    int tx = tid & 15, ty = tid >> 4;
    int m0 = ty * 4, n0 = tx * 8;
    ull acc[4][4];
#pragma unroll
    for (int i = 0; i < 4; i++)
#pragma unroll
        for (int j = 0; j < 4; j++) acc[i][j] = 0ull;

#pragma unroll 1
    for (int kc = 0; kc < 4; kc++) {
#pragma unroll
        for (int jj = 0; jj < 2; jj++) {
            int idx = tid + jj * 256;
            int m = idx >> 3, kq = idx & 7;
            float4 v = *(const float4*)(x + ((size_t)(b * 8192 + toks[m])) * 128 + kc * 32 + kq * 4);
            Xs[kq * 4 + 0][m] = v.x; Xs[kq * 4 + 1][m] = v.y;
            Xs[kq * 4 + 2][m] = v.z; Xs[kq * 4 + 3][m] = v.w;
        }
#pragma unroll
        for (int jj = 0; jj < 4; jj++) {
            int idx = tid + jj * 256;
            int c = idx >> 3, kq = idx & 7;
            float4 v = *(const float4*)(W + ((size_t)(nt * 128 + c)) * 128 + kc * 32 + kq * 4);
            Ws[kq * 4 + 0][c] = v.x; Ws[kq * 4 + 1][c] = v.y;
            Ws[kq * 4 + 2][c] = v.z; Ws[kq * 4 + 3][c] = v.w;
        }
        __syncthreads();
#pragma unroll
        for (int k = 0; k < 32; k++) {
            float4 xv = *(const float4*)&Xs[k][m0];
            ull xb0 = f2pk(xv.x, xv.x), xb1 = f2pk(xv.y, xv.y);
            ull xb2 = f2pk(xv.z, xv.z), xb3 = f2pk(xv.w, xv.w);
            const ull* wp = (const ull*)&Ws[k][n0];
            ull w0 = wp[0], w1 = wp[1], w2 = wp[2], w3 = wp[3];
            acc[0][0] = ffma2(xb0, w0, acc[0][0]); acc[0][1] = ffma2(xb0, w1, acc[0][1]);
            acc[0][2] = ffma2(xb0, w2, acc[0][2]); acc[0][3] = ffma2(xb0, w3, acc[0][3]);
            acc[1][0] = ffma2(xb1, w0, acc[1][0]); acc[1][1] = ffma2(xb1, w1, acc[1][1]);
            acc[1][2] = ffma2(xb1, w2, acc[1][2]); acc[1][3] = ffma2(xb1, w3, acc[1][3]);
            acc[2][0] = ffma2(xb2, w0, acc[2][0]); acc[2][1] = ffma2(xb2, w1, acc[2][1]);
            acc[2][2] = ffma2(xb2, w2, acc[2][2]); acc[2][3] = ffma2(xb2, w3, acc[2][3]);
            acc[3][0] = ffma2(xb3, w0, acc[3][0]); acc[3][1] = ffma2(xb3, w1, acc[3][1]);
            acc[3][2] = ffma2(xb3, w2, acc[3][2]); acc[3][3] = ffma2(xb3, w3, acc[3][3]);
        }
        __syncthreads();
    }

    // ---- fused epilogue ----
    int cb = nt >> 3, h = nt & 7;
    int cat = ty & 3;                             // 0=q 1=k 2=v 3=g (half-warp-uniform)
    int p = ty >> 2;
    int bh = b * 8 + h;
#pragma unroll
    for (int i = 0; i < 4; i++) {
        float r[8];
#pragma unroll
        for (int j = 0; j < 4; j++) {
            float2 f = f2up(acc[i][j]);
            r[2 * j] = f.x; r[2 * j + 1] = f.y;
        }
        int s0 = p * 16 + i * 4 + cb;             // row index within (b,h), 0..63
        int s = s0 + 1;
        if (cat < 2) {                            // q or k: rope + rmsnorm + tao
            float other[8];
#pragma unroll
            for (int c = 0; c < 8; c++) other[c] = __shfl_xor_sync(0xffffffffu, r[c], 8);
            int d0 = n0 & 63;
            float4 ca = *(const float4*)(cosb + s * 64 + d0);
            float4 cbv = *(const float4*)(cosb + s * 64 + d0 + 4);
            float4 sa = *(const float4*)(sinb + s * 64 + d0);
            float4 sb = *(const float4*)(sinb + s * 64 + d0 + 4);
            float cs[8] = {ca.x, ca.y, ca.z, ca.w, cbv.x, cbv.y, cbv.z, cbv.w};
            float sn[8] = {sa.x, sa.y, sa.z, sa.w, sb.x, sb.y, sb.z, sb.w};
            float sgn = (tx < 8) ? 1.f : -1.f;
            float rv[8], ssq = 0.f;
#pragma unroll
            for (int c = 0; c < 8; c++) {
                rv[c] = fmaf(r[c], cs[c], sgn * other[c] * sn[c]);
                ssq += rv[c] * rv[c];
            }
#pragma unroll
            for (int o = 8; o; o >>= 1) ssq += __shfl_xor_sync(0xffffffffu, ssq, o);
            float nrm = rsqrtf(ssq * (1.f / 128.f) + EPSF) * tao[cat];
            float* dst = (cat == 0 ? d_Qb : d_Kb) + ((size_t)bh * 65 + s) * 128 + n0;
            *(float4*)dst = make_float4(rv[0] * nrm, rv[1] * nrm, rv[2] * nrm, rv[3] * nrm);
            *(float4*)(dst + 4) = make_float4(rv[4] * nrm, rv[5] * nrm, rv[6] * nrm, rv[7] * nrm);
        } else if (cat == 2) {                    // v: raw
            float* dst = d_Vb + ((size_t)bh * 65 + s) * 128 + n0;
            *(float4*)dst = make_float4(r[0], r[1], r[2], r[3]);
            *(float4*)(dst + 4) = make_float4(r[4], r[5], r[6], r[7]);
        } else {                                  // g: raw gate logits
            float* dst = d_g + ((size_t)(b * 64 + s0)) * 1024 + h * 128 + n0;
            *(float4*)dst = make_float4(r[0], r[1], r[2], r[3]);
            *(float4*)(dst + 4) = make_float4(r[4], r[5], r[6], r[7]);
        }
    }
}

// ---------------- K5: causal attention, 4 row-chunks of 16 per (b,h) ----------------
// grid (4, 64), 256 threads (8 warps). Chunk handles query rows s = rbase+1..rbase+16,
// t extent = rbase+17. Warp owns 2 rows. Softmax is warp-parallel in registers.
__global__ __launch_bounds__(256) void k_attn() {
    __shared__ __align__(16) float Qc[32][18];    // [k][local row]
    __shared__ __align__(16) float Kc[32 * 68];   // [k][t]
    __shared__ __align__(16) float Ps[16 * 68];   // scores/probs
    int chunk = blockIdx.x, bh = blockIdx.y;
    int b = bh >> 3, h = bh & 7;
    int tid = threadIdx.x;
    int wid = tid >> 5, lane = tid & 31;
    int rbase = chunk * 16;
    int text = rbase + 17;                        // 17 / 33 / 49 / 65
    const float* Qg = d_Qb + (size_t)bh * 65 * 128;
    const float* Kg = d_Kb + (size_t)bh * 65 * 128;
    const float* Vg = d_Vb + (size_t)bh * 65 * 128;
    int r0 = wid * 2;                             // local rows r0, r0+1
    int t0 = lane * 2;
    ull acc0 = 0ull, acc1 = 0ull;
    float e64 = 0.f;

#pragma unroll 1
    for (int kc = 0; kc < 4; kc++) {
        if (tid < 128) {                          // Q: 16 rows x 8 float4
            int r = tid >> 3, kq = tid & 7;
            float4 qv = *(const float4*)(Qg + (size_t)(rbase + r + 1) * 128 + kc * 32 + kq * 4);
            Qc[kq * 4 + 0][r] = qv.x; Qc[kq * 4 + 1][r] = qv.y;
            Qc[kq * 4 + 2][r] = qv.z; Qc[kq * 4 + 3][r] = qv.w;
        }
        for (int idx = tid; idx < text * 8; idx += 256) {
            int t = idx >> 3, kq = idx & 7;
            float4 kv = *(const float4*)(Kg + (size_t)t * 128 + kc * 32 + kq * 4);
            Kc[(kq * 4 + 0) * 68 + t] = kv.x; Kc[(kq * 4 + 1) * 68 + t] = kv.y;
            Kc[(kq * 4 + 2) * 68 + t] = kv.z; Kc[(kq * 4 + 3) * 68 + t] = kv.w;
        }
        __syncthreads();
#pragma unroll
        for (int k = 0; k < 32; k++) {
            ull qp = *(const ull*)&Qc[k][r0];      // rows r0, r0+1 (broadcast)
            float2 kv = *(const float2*)&Kc[k * 68 + t0];
            acc0 = ffma2(qp, f2pk(kv.x, kv.x), acc0);
            acc1 = ffma2(qp, f2pk(kv.y, kv.y), acc1);
        }
        if (chunk == 3 && tid == 0) {              // lone (s=64, t=64) element
#pragma unroll
            for (int k = 0; k < 32; k++) e64 += Qc[k][15] * Kc[k * 68 + 64];
        }
        __syncthreads();
    }
    {   // store raw scores
        float2 f0 = f2up(acc0), f1 = f2up(acc1);
        Ps[r0 * 68 + t0]           = f0.x;
        Ps[(r0 + 1) * 68 + t0]     = f0.y;
        Ps[r0 * 68 + t0 + 1]       = f1.x;
        Ps[(r0 + 1) * 68 + t0 + 1] = f1.y;
        if (chunk == 3 && tid == 0) Ps[15 * 68 + 64] = e64;
    }
    __syncthreads();

    // warp-parallel softmax: warp wid owns local rows r0, r0+1
    const float scl = 0.08838834764831845f;       // 1/sqrt(128)
#pragma unroll
    for (int rr = 0; rr < 2; rr++) {
        int lr = r0 + rr;
        int s = rbase + lr + 1;
        bool ok0 = (lane <= s);
        bool ok1 = (lane + 32 <= s);
        float v0 = ok0 ? Ps[lr * 68 + lane] * scl : -1e30f;
        float v1 = ok1 ? Ps[lr * 68 + lane + 32] * scl : -1e30f;
        float ve = (s == 64) ? Ps[lr * 68 + 64] * scl : -1e30f;   // warp-uniform
        float m = fmaxf(v0, v1);
#pragma unroll
        for (int o = 16; o; o >>= 1) m = fmaxf(m, __shfl_xor_sync(0xffffffffu, m, o));
        m = fmaxf(m, ve);
        float e0 = ok0 ? __expf(v0 - m) : 0.f;
        float e1 = ok1 ? __expf(v1 - m) : 0.f;
        float ee = (s == 64) ? __expf(ve - m) : 0.f;
        float sum = e0 + e1;
#pragma unroll
        for (int o = 16; o; o >>= 1) sum += __shfl_xor_sync(0xffffffffu, sum, o);
        sum += ee;
        float inv = 1.f / sum;
        Ps[lr * 68 + lane]      = e0 * inv;
        Ps[lr * 68 + lane + 32] = e1 * inv;
        if (lane == 0) Ps[lr * 68 + 64] = ee * inv;
    }
    __syncwarp();                                  // own-row Ps now consistent within warp

    // PV: warp's 2 rows; lane owns channels c0..c0+3; V straight from global (L1-shared)
    int c0 = lane * 4;
    ull y00 = 0ull, y01 = 0ull, y10 = 0ull, y11 = 0ull;
    const float* P0 = &Ps[r0 * 68];
    const float* P1 = &Ps[(r0 + 1) * 68];
#pragma unroll 4
    for (int t = 0; t < text; t++) {
        const ull* vp = (const ull*)(Vg + (size_t)t * 128 + c0);
        ull v0 = vp[0], v1 = vp[1];
        float p0 = P0[t], p1 = P1[t];
        ull pb0 = f2pk(p0, p0), pb1 = f2pk(p1, p1);
        y00 = ffma2(pb0, v0, y00); y01 = ffma2(pb0, v1, y01);
        y10 = ffma2(pb1, v0, y10); y11 = ffma2(pb1, v1, y11);
    }

    // gate with sigmoid(g) and store (rows rbase+r0, rbase+r0+1)
#pragma unroll
    for (int rr = 0; rr < 2; rr++) {
        int r = rbase + r0 + rr;
        float4 g4 = *(const float4*)(d_g + ((size_t)(b * 64 + r)) * 1024 + h * 128 + c0);
        float2 ya = f2up(rr ? y10 : y00), yb = f2up(rr ? y11 : y01);
        float4 o;
        o.x = ya.x / (1.f + __expf(-g4.x));
        o.y = ya.y / (1.f + __expf(-g4.y));
        o.z = yb.x / (1.f + __expf(-g4.z));
        o.w = yb.y / (1.f + __expf(-g4.w));
        *(float4*)(d_yg + ((size_t)(b * 64 + r)) * 1024 + h * 128 + c0) = o;
    }
}

// ---------------- K6: output GEMM, split-K=8, atomicAdd into out (f32x2) ----------------
__global__ __launch_bounds__(128) void k_out(const float* __restrict__ Wout,
                                             float* __restrict__ out) {
    int mt = blockIdx.x, nt = blockIdx.y, kc = blockIdx.z;
    __shared__ __align__(16) float Ys[32][68];
    __shared__ __align__(16) float Ws[32][68];
    int tid = threadIdx.x;
    int tx = tid & 7, ty = tid >> 3;
    int m0 = ty * 4, n0 = tx * 8;
    ull acc[4][4];
#pragma unroll
    for (int i = 0; i < 4; i++)
#pragma unroll
        for (int j = 0; j < 4; j++) acc[i][j] = 0ull;

#pragma unroll 1
    for (int ck = 0; ck < 4; ck++) {
        int kbase = kc * 128 + ck * 32;
#pragma unroll
        for (int jj = 0; jj < 4; jj++) {
            int idx = tid + jj * 128;
            int m = idx >> 3, kq = idx & 7;
            float4 v = *(const float4*)(d_yg + (size_t)(mt * 64 + m) * 1024 + kbase + kq * 4);
            Ys[kq * 4 + 0][m] = v.x; Ys[kq * 4 + 1][m] = v.y;
            Ys[kq * 4 + 2][m] = v.z; Ys[kq * 4 + 3][m] = v.w;
            float4 w = *(const float4*)(Wout + (size_t)(nt * 64 + m) * 1024 + kbase + kq * 4);
            Ws[kq * 4 + 0][m] = w.x; Ws[kq * 4 + 1][m] = w.y;
            Ws[kq * 4 + 2][m] = w.z; Ws[kq * 4 + 3][m] = w.w;
        }
        __syncthreads();
#pragma unroll
        for (int k = 0; k < 32; k++) {
            float4 yv = *(const float4*)&Ys[k][m0];
            ull yb0 = f2pk(yv.x, yv.x), yb1 = f2pk(yv.y, yv.y);
            ull yb2 = f2pk(yv.z, yv.z), yb3 = f2pk(yv.w, yv.w);
            const ull* wp = (const ull*)&Ws[k][n0];
            ull w0 = wp[0], w1 = wp[1], w2 = wp[2], w3 = wp[3];
            acc[0][0] = ffma2(yb0, w0, acc[0][0]); acc[0][1] = ffma2(yb0, w1, acc[0][1]);
            acc[0][2] = ffma2(yb0, w2, acc[0][2]); acc[0][3] = ffma2(yb0, w3, acc[0][3]);
            acc[1][0] = ffma2(yb1, w0, acc[1][0]); acc[1][1] = ffma2(yb1, w1, acc[1][1]);
            acc[1][2] = ffma2(yb1, w2, acc[1][2]); acc[1][3] = ffma2(yb1, w3, acc[1][3]);
            acc[2][0] = ffma2(yb2, w0, acc[2][0]); acc[2][1] = ffma2(yb2, w1, acc[2][1]);
            acc[2][2] = ffma2(yb2, w2, acc[2][2]); acc[2][3] = ffma2(yb2, w3, acc[2][3]);
            acc[3][0] = ffma2(yb3, w0, acc[3][0]); acc[3][1] = ffma2(yb3, w1, acc[3][1]);
            acc[3][2] = ffma2(yb3, w2, acc[3][2]); acc[3][3] = ffma2(yb3, w3, acc[3][3]);
        }
        __syncthreads();
    }
#pragma unroll
    for (int i = 0; i < 4; i++) {
        float* dst = out + (size_t)(mt * 64 + m0 + i) * 128 + nt * 64 + n0;
#pragma unroll
        for (int j = 0; j < 4; j++) {
            float2 f = f2up(acc[i][j]);
            atomicAdd(dst + 2 * j,     f.x);
            atomicAdd(dst + 2 * j + 1, f.y);
        }
    }
}

// ---------------- launch ----------------
extern "C" void kernel_launch(void* const* d_in, const int* in_sizes, int n_in,
                              void* d_out, int out_size) {
    const float* x     = (const float*)d_in[0];
    const float* cosb  = (const float*)d_in[1];
    const float* sinb  = (const float*)d_in[2];
    const float* sink  = (const float*)d_in[3];
    const float* Wqkvg = (const float*)d_in[4];
    const float* pw    = (const float*)d_in[5];
    const float* Wout  = (const float*)d_in[6];
    const float* tao   = (const float*)d_in[7];
    float* out = (float*)d_out;

    cudaMemsetAsync(out, 0, (size_t)out_size * sizeof(float));
    k_score<<<512, 256>>>(x, pw);
    k_topk_sink<<<2, 256>>>(sink, tao);
    k_qkvg<<<dim3(32, 8), 256>>>(x, Wqkvg, cosb, sinb, tao);
    k_attn<<<dim3(4, 64), 256>>>();
    k_out<<<dim3(8, 2, 8), 128>>>(Wout, out);
}